// round 13
// baseline (speedup 1.0000x reference)
#include <cuda_runtime.h>
#include <cstdint>

// SiLU(x) = x * sigmoid(x). HBM-bound streaming op.
// R13: final block-size probe. Identical per-thread shape to the R9/R12
// Pareto-best (2x 256-bit cs loads + 2x 256-bit cs stores per thread), but
// TPB=512: grid halves to 8192, halving CTA-dispatch/wave-transition events
// while keeping MLP, register count (~32), and occupancy unchanged.

__device__ __forceinline__ float silu1(float x) {
    return x * (1.0f / (1.0f + __expf(-x)));
}

struct f8 { float v[8]; };

// 256-bit streaming load: 8 floats, evict-first.
__device__ __forceinline__ f8 ldg_cs_256(const void* p) {
    unsigned long long a, b, c, d;
    asm volatile("ld.global.cs.v4.b64 {%0,%1,%2,%3}, [%4];"
                 : "=l"(a), "=l"(b), "=l"(c), "=l"(d) : "l"(p));
    f8 r;
    r.v[0] = __uint_as_float((unsigned)a);  r.v[1] = __uint_as_float((unsigned)(a >> 32));
    r.v[2] = __uint_as_float((unsigned)b);  r.v[3] = __uint_as_float((unsigned)(b >> 32));
    r.v[4] = __uint_as_float((unsigned)c);  r.v[5] = __uint_as_float((unsigned)(c >> 32));
    r.v[6] = __uint_as_float((unsigned)d);  r.v[7] = __uint_as_float((unsigned)(d >> 32));
    return r;
}

// 256-bit streaming store: 8 floats.
__device__ __forceinline__ void stg_cs_256(void* p, const f8& r) {
    unsigned long long a = ((unsigned long long)__float_as_uint(r.v[1]) << 32) | __float_as_uint(r.v[0]);
    unsigned long long b = ((unsigned long long)__float_as_uint(r.v[3]) << 32) | __float_as_uint(r.v[2]);
    unsigned long long c = ((unsigned long long)__float_as_uint(r.v[5]) << 32) | __float_as_uint(r.v[4]);
    unsigned long long d = ((unsigned long long)__float_as_uint(r.v[7]) << 32) | __float_as_uint(r.v[6]);
    asm volatile("st.global.cs.v4.b64 [%0], {%1,%2,%3,%4};"
                 :: "l"(p), "l"(a), "l"(b), "l"(c), "l"(d) : "memory");
}

__device__ __forceinline__ f8 silu8(f8 x) {
    f8 r;
#pragma unroll
    for (int i = 0; i < 8; i++) r.v[i] = silu1(x.v[i]);
    return r;
}

#define TPB 512
#define HALF_BYTES (TPB * 32)          // 16KB per half
#define CHUNK_BYTES (HALF_BYTES * 2)   // 32KB per block
#define CHUNK_VECS (CHUNK_BYTES / 16)  // float4 units for host math

// Exact-coverage: each thread does 2 x 32B loads, front-batched.
__global__ void __launch_bounds__(TPB) silu_v256_b512(const float* __restrict__ in,
                                                      float* __restrict__ out) {
    const char* cin = (const char*)in + (size_t)blockIdx.x * CHUNK_BYTES;
    char* cout = (char*)out + (size_t)blockIdx.x * CHUNK_BYTES;
    unsigned off0 = threadIdx.x * 32u;
    unsigned off1 = off0 + (unsigned)HALF_BYTES;

    f8 a = ldg_cs_256(cin + off0);
    f8 b = ldg_cs_256(cin + off1);

    stg_cs_256(cout + off0, silu8(a));
    stg_cs_256(cout + off1, silu8(b));
}

// Guarded fallback (float4 granularity) for shapes that don't divide evenly.
__global__ void __launch_bounds__(256) silu_guard(const float4* __restrict__ in,
                                                  float4* __restrict__ out,
                                                  int n_vec) {
    int base = blockIdx.x * (256 * 4) + threadIdx.x;
#pragma unroll
    for (int k = 0; k < 4; k++) {
        int i = base + k * 256;
        if (i < n_vec) {
            float4 v = __ldcs(&in[i]);
            float4 r;
            r.x = silu1(v.x); r.y = silu1(v.y); r.z = silu1(v.z); r.w = silu1(v.w);
            __stcs(&out[i], r);
        }
    }
}

// Scalar tail (n not divisible by 4; not hit for this shape)
__global__ void silu_tail(const float* __restrict__ in, float* __restrict__ out,
                          int start, int n) {
    int i = start + blockIdx.x * blockDim.x + threadIdx.x;
    if (i < n) {
        float x = in[i];
        out[i] = x * (1.0f / (1.0f + __expf(-x)));
    }
}

extern "C" void kernel_launch(void* const* d_in, const int* in_sizes, int n_in,
                              void* d_out, int out_size) {
    const float* x = (const float*)d_in[0];
    float* y = (float*)d_out;
    int n = in_sizes[0];

    int n_vec = n / 4;

    if (n_vec % CHUNK_VECS == 0) {
        int blocks = n_vec / CHUNK_VECS;     // 8192 for this shape
        silu_v256_b512<<<blocks, TPB>>>(x, y);
    } else {
        int blocks = (n_vec + 256 * 4 - 1) / (256 * 4);
        silu_guard<<<blocks, 256>>>((const float4*)x, (float4*)y, n_vec);
    }

    int rem = n - n_vec * 4;
    if (rem > 0) {
        silu_tail<<<1, 256>>>(x, y, n_vec * 4, n);
    }
}